// round 3
// baseline (speedup 1.0000x reference)
#include <cuda_runtime.h>
#include <cstdint>

#define SEQN 65536
#define HN   128
#define G4   512   // 4*H

typedef unsigned long long u64;

// Scratch (device globals: allocation-free per harness rules)
__device__ float g_GA[(size_t)SEQN * G4];   // precomputed x@WA1^T + bA1 + bA2
__device__ float g_HB[(size_t)SEQN * HN];   // hB per step, consumed by fc GEMM

// ---------------------------------------------------------------------------
// helpers
// ---------------------------------------------------------------------------
__device__ __forceinline__ float sigm(float x) {
    return __fdividef(1.f, 1.f + __expf(-x));
}
__device__ __forceinline__ float tanh_(float x) {
    return 2.f * sigm(2.f * x) - 1.f;
}

__device__ __forceinline__ uint32_t mapa_u32(const void* p, int rank) {
    uint32_t a = (uint32_t)__cvta_generic_to_shared(p), r;
    asm("mapa.shared::cluster.u32 %0, %1, %2;" : "=r"(r) : "r"(a), "r"(rank));
    return r;
}

#define ST_CLUSTER(addr, v) \
    asm volatile("st.shared::cluster.f32 [%0], %1;" :: "r"(addr), "f"(v) : "memory")

#define ARRIVE_CLUSTER(addr) \
    asm volatile("mbarrier.arrive.release.cluster.shared::cluster.b64 _, [%0];" \
                 :: "r"(addr) : "memory")

#define MBAR_INIT(addr, cnt) \
    asm volatile("mbarrier.init.shared.b64 [%0], %1;" :: "r"(addr), "r"(cnt) : "memory")

__device__ __forceinline__ void wait_parity(uint32_t mbar, uint32_t par) {
    uint32_t done;
    do {
        asm volatile(
            "{\n\t.reg .pred p;\n\t"
            "mbarrier.try_wait.parity.acquire.cluster.shared::cta.b64 p, [%1], %2, 0x989680;\n\t"
            "selp.b32 %0, 1, 0, p;\n\t}"
            : "=r"(done) : "r"(mbar), "r"(par) : "memory");
    } while (!done);
}

#define FMA2(acc, w, h) \
    asm("fma.rn.f32x2 %0, %1, %2, %0;" : "+l"(acc) : "l"(w), "l"(h))

#define CLUSTER_SYNC_()                                                        \
    do {                                                                       \
        asm volatile("barrier.cluster.arrive.aligned;" ::: "memory");          \
        asm volatile("barrier.cluster.wait.aligned;"   ::: "memory");          \
    } while (0)

// ---------------------------------------------------------------------------
// Kernel 1: GA[t, 512] = x[t] @ WA1^T + bA1 + bA2
// ---------------------------------------------------------------------------
__global__ void __launch_bounds__(128) ga_kernel(const float* __restrict__ x,
                                                 const float* __restrict__ W,
                                                 const float* __restrict__ b1,
                                                 const float* __restrict__ b2) {
    __shared__ float xs[64 * 128];
    const int tid = threadIdx.x;
    const int row = (blockIdx.y << 7) + tid;

    float4 w[32];
    const float4* wg = (const float4*)(W + (size_t)row * 128);
#pragma unroll
    for (int k = 0; k < 32; k++) w[k] = wg[k];
    const float bias = b1[row] + b2[row];

    const int t0 = blockIdx.x * 64;
    const float4* xg = (const float4*)(x + (size_t)t0 * 128);
    float4* xs4 = (float4*)xs;
#pragma unroll
    for (int i = 0; i < 16; i++) xs4[tid + (i << 7)] = xg[tid + (i << 7)];
    __syncthreads();

    for (int tt = 0; tt < 64; tt++) {
        const float4* hx = (const float4*)(xs + tt * 128);
        float a0 = 0.f, a1 = 0.f, a2 = 0.f, a3 = 0.f;
#pragma unroll
        for (int k = 0; k < 32; k++) {
            float4 h = hx[k];
            a0 = fmaf(w[k].x, h.x, a0);
            a1 = fmaf(w[k].y, h.y, a1);
            a2 = fmaf(w[k].z, h.z, a2);
            a3 = fmaf(w[k].w, h.w, a3);
        }
        g_GA[(size_t)(t0 + tt) * G4 + row] = (a0 + a1) + (a2 + a3) + bias;
    }
}

// ---------------------------------------------------------------------------
// Kernel 2: pipelined recurrence, mbarrier-synced, FFMA2 matvec.
// 8-CTA cluster, 384 threads. B runs one tick behind A (see R2).
// Sync: 2 alternating mbarriers per CTA, count=256 (32 producer lanes x 8
// CTAs). Producers: remote st.shared::cluster then release-arrive to every
// CTA's bar[t&1]; everyone try_waits with parity (t>>1)&1.
// ---------------------------------------------------------------------------
__global__ void __cluster_dims__(8, 1, 1) __launch_bounds__(384, 1)
recur_kernel(const float* __restrict__ WA2, const float* __restrict__ WB1,
             const float* __restrict__ WB2, const float* __restrict__ bB1,
             const float* __restrict__ bB2, const float* __restrict__ hA0,
             const float* __restrict__ cA0, const float* __restrict__ hB0,
             const float* __restrict__ cB0, float* __restrict__ out,
             int write_states) {
    __shared__ alignas(16) float s_hA[2][HN];
    __shared__ alignas(16) float s_hB[2][HN];
    __shared__ float s_uA[64];   // WA2 dots (+GA)
    __shared__ float s_wB[64];   // WB1 dots
    __shared__ float s_vB[64];   // WB2 dots
    __shared__ float s_bb[64];   // bB1+bB2
    __shared__ alignas(8) u64 s_bar[2];

    const int c    = blockIdx.x;
    const int tid  = threadIdx.x;
    const int rs   = tid >> 1;      // 0..191
    const int half = tid & 1;
    const int mat  = rs >> 6;       // 0:WA2 1:WB1 2:WB2
    const int r    = rs & 63;
    const int grow = ((r >> 4) << 7) + (c << 4) + (r & 15);

    // ---- weights as packed f32x2 (64-bit lanes) ----
    const float* Wp = (mat == 0) ? WA2 : (mat == 1) ? WB1 : WB2;
    u64 wv[32];
    {
        const ulonglong2* wg = (const ulonglong2*)(Wp + (size_t)grow * 128 + half * 64);
#pragma unroll
        for (int k = 0; k < 16; k++) { ulonglong2 q = wg[k]; wv[2*k] = q.x; wv[2*k+1] = q.y; }
    }

    // ---- init SMEM ----
    if (tid < 64) {
        const int gr = ((tid >> 4) << 7) + (c << 4) + (tid & 15);
        s_bb[tid] = bB1[gr] + bB2[gr];
    }
    if (tid < HN) {
        s_hA[0][tid] = hA0[tid];
        s_hB[0][tid] = 0.f;       // read (discarded) at tick 0
        s_hB[1][tid] = hB0[tid];  // read at tick 1
    }
    if (tid == 0) {
        uint32_t b0 = (uint32_t)__cvta_generic_to_shared(&s_bar[0]);
        uint32_t b1a = (uint32_t)__cvta_generic_to_shared(&s_bar[1]);
        MBAR_INIT(b0, 256);
        MBAR_INIT(b1a, 256);
    }
    const bool isA = (tid < 16);
    const bool isB = (tid >= 32 && tid < 48);
    float cAr = 0.f, cBr = 0.f, hB_init = 0.f;
    if (isA) cAr = cA0[(c << 4) + tid];
    if (isB) { cBr = cB0[(c << 4) + tid - 32]; hB_init = hB0[(c << 4) + tid - 32]; }
    __syncthreads();
    CLUSTER_SYNC_();   // all barriers initialized before any remote arrive

    // ---- producer precomputed remote addresses ----
    uint32_t pdst[2][8];   // [buffer][rank] -> h slot
    uint32_t bdst[2][8];   // [bar index][rank]
    if (isA || isB) {
        const int jj = isA ? tid : (tid - 32);
        const int j  = (c << 4) + jj;
#pragma unroll
        for (int buf = 0; buf < 2; buf++) {
            const float* base = isA ? &s_hA[buf][j] : &s_hB[buf][j];
#pragma unroll
            for (int rk = 0; rk < 8; rk++) pdst[buf][rk] = mapa_u32(base, rk);
        }
#pragma unroll
        for (int bi = 0; bi < 2; bi++)
#pragma unroll
            for (int rk = 0; rk < 8; rk++) bdst[bi][rk] = mapa_u32(&s_bar[bi], rk);
    }
    uint32_t bloc[2];
    bloc[0] = (uint32_t)__cvta_generic_to_shared(&s_bar[0]);
    bloc[1] = (uint32_t)__cvta_generic_to_shared(&s_bar[1]);

    // ---- GA prefetch (mat==0 half==0 lanes) ----
    const bool is_ga = (mat == 0) && (half == 0);
    float ga_cur = 0.f, ga_next = 0.f;
    if (is_ga) ga_cur = g_GA[grow];

    const size_t OH = (size_t)SEQN * HN;

    for (int t = 0; t <= SEQN; t++) {
        const int pb = t & 1;
        if (is_ga)
            ga_next = (t + 1 < SEQN) ? __ldg(&g_GA[(size_t)(t + 1) * G4 + grow]) : 0.f;

        // ===== merged matvec (FFMA2) =====
        {
            const float* hsrc = (mat == 2) ? s_hB[pb] : s_hA[pb];
            const ulonglong2* hv = (const ulonglong2*)(hsrc + half * 64);
            u64 a0 = 0ULL, a1 = 0ULL;
#pragma unroll
            for (int k = 0; k < 16; k++) {
                ulonglong2 h2 = hv[k];
                FMA2(a0, wv[2*k],     h2.x);
                FMA2(a1, wv[2*k + 1], h2.y);
            }
            float2 f0 = *(float2*)&a0, f1 = *(float2*)&a1;
            float s = (f0.x + f0.y) + (f1.x + f1.y);
            s += __shfl_down_sync(0xffffffffu, s, 1);
            if (half == 0) {
                if (mat == 0)      s_uA[r] = s + ga_cur;
                else if (mat == 1) s_wB[r] = s;
                else               s_vB[r] = s;
            }
        }
        __syncthreads();

        // ===== cell A (step t) =====
        if (isA) {
            const float gi = s_uA[tid];
            const float gf = s_uA[16 + tid];
            const float gg = s_uA[32 + tid];
            const float go = s_uA[48 + tid];
            const float cn = sigm(gf) * cAr + sigm(gi) * tanh_(gg);
            cAr = cn;
            const float h = sigm(go) * tanh_(cn);
#pragma unroll
            for (int rk = 0; rk < 8; rk++) ST_CLUSTER(pdst[pb ^ 1][rk], h);
#pragma unroll
            for (int rk = 0; rk < 8; rk++) ARRIVE_CLUSTER(bdst[pb][rk]);
            if (write_states && t == SEQN - 1) {
                const int j = (c << 4) + tid;
                out[OH + j]      = h;
                out[OH + HN + j] = cn;
            }
        }

        // ===== cell B (step t-1) =====
        if (isB) {
            const int ln = tid - 32;
            float h, cn = cBr;
            if (t == 0) {
                h = hB_init;
            } else {
                const float gi = s_wB[ln]      + s_vB[ln]      + s_bb[ln];
                const float gf = s_wB[16 + ln] + s_vB[16 + ln] + s_bb[16 + ln];
                const float gg = s_wB[32 + ln] + s_vB[32 + ln] + s_bb[32 + ln];
                const float go = s_wB[48 + ln] + s_vB[48 + ln] + s_bb[48 + ln];
                cn = sigm(gf) * cBr + sigm(gi) * tanh_(gg);
                cBr = cn;
                h = sigm(go) * tanh_(cn);
            }
#pragma unroll
            for (int rk = 0; rk < 8; rk++) ST_CLUSTER(pdst[pb ^ 1][rk], h);
#pragma unroll
            for (int rk = 0; rk < 8; rk++) ARRIVE_CLUSTER(bdst[pb][rk]);
            if (t >= 1) {
                const int j = (c << 4) + ln;
                g_HB[(size_t)(t - 1) * HN + j] = h;
                if (write_states && t == SEQN) {
                    out[OH + 2 * HN + j] = h;
                    out[OH + 3 * HN + j] = cn;
                }
            }
        }

        // ===== tick barrier =====
        wait_parity(bloc[pb], (uint32_t)((t >> 1) & 1));
        if (is_ga) ga_cur = ga_next;
    }
}

// ---------------------------------------------------------------------------
// Kernel 3: logits[t] = hB[t] @ Wfc^T + bfc
// ---------------------------------------------------------------------------
__global__ void __launch_bounds__(128) fc_kernel(const float* __restrict__ W,
                                                 const float* __restrict__ b,
                                                 float* __restrict__ out) {
    __shared__ float hs[64 * 128];
    const int tid = threadIdx.x;

    float4 w[32];
    const float4* wg = (const float4*)(W + (size_t)tid * 128);
#pragma unroll
    for (int k = 0; k < 32; k++) w[k] = wg[k];
    const float bias = b[tid];

    const int t0 = blockIdx.x * 64;
    const float4* hg = (const float4*)(g_HB + (size_t)t0 * 128);
    float4* hs4 = (float4*)hs;
#pragma unroll
    for (int i = 0; i < 16; i++) hs4[tid + (i << 7)] = hg[tid + (i << 7)];
    __syncthreads();

    for (int tt = 0; tt < 64; tt++) {
        const float4* hx = (const float4*)(hs + tt * 128);
        float a0 = 0.f, a1 = 0.f, a2 = 0.f, a3 = 0.f;
#pragma unroll
        for (int k = 0; k < 32; k++) {
            float4 h = hx[k];
            a0 = fmaf(w[k].x, h.x, a0);
            a1 = fmaf(w[k].y, h.y, a1);
            a2 = fmaf(w[k].z, h.z, a2);
            a3 = fmaf(w[k].w, h.w, a3);
        }
        out[(size_t)(t0 + tt) * 128 + tid] = (a0 + a1) + (a2 + a3) + bias;
    }
}

// ---------------------------------------------------------------------------
// launch
// ---------------------------------------------------------------------------
extern "C" void kernel_launch(void* const* d_in, const int* in_sizes, int n_in,
                              void* d_out, int out_size) {
    const float* x   = (const float*)d_in[0];
    const float* hA0 = (const float*)d_in[1];
    const float* cA0 = (const float*)d_in[2];
    const float* hB0 = (const float*)d_in[3];
    const float* cB0 = (const float*)d_in[4];
    const float* WA1 = (const float*)d_in[5];
    const float* bA1 = (const float*)d_in[6];
    const float* WA2 = (const float*)d_in[7];
    const float* bA2 = (const float*)d_in[8];
    const float* WB1 = (const float*)d_in[9];
    const float* bB1 = (const float*)d_in[10];
    const float* WB2 = (const float*)d_in[11];
    const float* bB2 = (const float*)d_in[12];
    const float* Wfc = (const float*)d_in[13];
    const float* bfc = (const float*)d_in[14];
    float* out = (float*)d_out;

    const int write_states = (out_size >= SEQN * HN + 4 * HN) ? 1 : 0;

    ga_kernel<<<dim3(SEQN / 64, 4), 128>>>(x, WA1, bA1, bA2);
    recur_kernel<<<8, 384>>>(WA2, WB1, WB2, bB1, bB2, hA0, cA0, hB0, cB0, out,
                             write_states);
    fc_kernel<<<SEQN / 64, 128>>>(Wfc, bfc, out);
}

// round 4
// speedup vs baseline: 1.3042x; 1.3042x over previous
#include <cuda_runtime.h>
#include <cstdint>

#define SEQN 65536
#define HN   128
#define G4   512   // 4*H

typedef unsigned long long u64;

// Scratch (device globals: allocation-free per harness rules)
__device__ float g_GA[(size_t)SEQN * G4];   // precomputed x@WA1^T + bA1 + bA2
__device__ float g_HB[(size_t)SEQN * HN];   // hB per step, consumed by fc GEMM

// ---------------------------------------------------------------------------
// helpers
// ---------------------------------------------------------------------------
__device__ __forceinline__ float sigm(float x) {
    return __fdividef(1.f, 1.f + __expf(-x));
}
__device__ __forceinline__ float tanh_(float x) {
    return 2.f * sigm(2.f * x) - 1.f;
}

__device__ __forceinline__ uint32_t mapa_u32(const void* p, int rank) {
    uint32_t a = (uint32_t)__cvta_generic_to_shared(p), r;
    asm("mapa.shared::cluster.u32 %0, %1, %2;" : "=r"(r) : "r"(a), "r"(rank));
    return r;
}

// single indivisible 8B store: {h, tag} — tag visible => h visible
__device__ __forceinline__ void st_msg(uint32_t addr, float h, uint32_t tag) {
    u64 m;
    asm("mov.b64 %0, {%1, %2};" : "=l"(m) : "f"(h), "r"(tag));
    asm volatile("st.shared::cluster.b64 [%0], %1;" :: "r"(addr), "l"(m) : "memory");
}

__device__ __forceinline__ u64 ld_msg(uint32_t addr) {
    u64 v;
    asm volatile("ld.volatile.shared.b64 %0, [%1];" : "=l"(v) : "r"(addr));
    return v;
}

#define FMA2(acc, w, h) \
    asm("fma.rn.f32x2 %0, %1, %2, %0;" : "+l"(acc) : "l"(w), "l"(h))

#define CLUSTER_SYNC_()                                                        \
    do {                                                                       \
        asm volatile("barrier.cluster.arrive.aligned;" ::: "memory");          \
        asm volatile("barrier.cluster.wait.aligned;"   ::: "memory");          \
    } while (0)

// ---------------------------------------------------------------------------
// Kernel 1: GA[t, 512] = x[t] @ WA1^T + bA1 + bA2
// ---------------------------------------------------------------------------
__global__ void __launch_bounds__(128) ga_kernel(const float* __restrict__ x,
                                                 const float* __restrict__ W,
                                                 const float* __restrict__ b1,
                                                 const float* __restrict__ b2) {
    __shared__ float xs[64 * 128];
    const int tid = threadIdx.x;
    const int row = (blockIdx.y << 7) + tid;

    float4 w[32];
    const float4* wg = (const float4*)(W + (size_t)row * 128);
#pragma unroll
    for (int k = 0; k < 32; k++) w[k] = wg[k];
    const float bias = b1[row] + b2[row];

    const int t0 = blockIdx.x * 64;
    const float4* xg = (const float4*)(x + (size_t)t0 * 128);
    float4* xs4 = (float4*)xs;
#pragma unroll
    for (int i = 0; i < 16; i++) xs4[tid + (i << 7)] = xg[tid + (i << 7)];
    __syncthreads();

    for (int tt = 0; tt < 64; tt++) {
        const float4* hx = (const float4*)(xs + tt * 128);
        float a0 = 0.f, a1 = 0.f, a2 = 0.f, a3 = 0.f;
#pragma unroll
        for (int k = 0; k < 32; k++) {
            float4 h = hx[k];
            a0 = fmaf(w[k].x, h.x, a0);
            a1 = fmaf(w[k].y, h.y, a1);
            a2 = fmaf(w[k].z, h.z, a2);
            a3 = fmaf(w[k].w, h.w, a3);
        }
        g_GA[(size_t)(t0 + tt) * G4 + row] = (a0 + a1) + (a2 + a3) + bias;
    }
}

// ---------------------------------------------------------------------------
// Kernel 2: pipelined recurrence. 8-CTA cluster, 384 threads.
// B runs one tick behind A (R2 pipelining). Sync = tag-carrying payloads:
// producers store {h, tick} as ONE 8B st.shared::cluster per rank; 256
// spinner threads poll one slot each until tag==t-1, copy h into contiguous
// lin buffers, __syncthreads, matvec (FFMA2). No barriers in steady state.
// ---------------------------------------------------------------------------
__global__ void __cluster_dims__(8, 1, 1) __launch_bounds__(384, 1)
recur_kernel(const float* __restrict__ WA2, const float* __restrict__ WB1,
             const float* __restrict__ WB2, const float* __restrict__ bB1,
             const float* __restrict__ bB2, const float* __restrict__ hA0,
             const float* __restrict__ cA0, const float* __restrict__ hB0,
             const float* __restrict__ cB0, float* __restrict__ out,
             int write_states) {
    __shared__ alignas(16) float2 s_msgA[2][HN];   // {h, tag}
    __shared__ alignas(16) float2 s_msgB[2][HN];
    __shared__ alignas(16) float s_hA[HN];         // linear h for matvec
    __shared__ alignas(16) float s_hB[HN];
    __shared__ float s_uA[64];   // WA2 dots (+GA)
    __shared__ float s_wB[64];   // WB1 dots
    __shared__ float s_vB[64];   // WB2 dots
    __shared__ float s_bb[64];   // bB1+bB2

    const int c    = blockIdx.x;
    const int tid  = threadIdx.x;
    const int rs   = tid >> 1;      // 0..191
    const int half = tid & 1;
    const int mat  = rs >> 6;       // 0:WA2 1:WB1 2:WB2
    const int r    = rs & 63;
    const int grow = ((r >> 4) << 7) + (c << 4) + (r & 15);

    // ---- weights as packed f32x2 ----
    const float* Wp = (mat == 0) ? WA2 : (mat == 1) ? WB1 : WB2;
    u64 wv[32];
    {
        const ulonglong2* wg = (const ulonglong2*)(Wp + (size_t)grow * 128 + half * 64);
#pragma unroll
        for (int k = 0; k < 16; k++) { ulonglong2 q = wg[k]; wv[2*k] = q.x; wv[2*k+1] = q.y; }
    }

    // ---- init SMEM (every CTA inits its own msg buffers) ----
    if (tid < 64) {
        const int gr = ((tid >> 4) << 7) + (c << 4) + (tid & 15);
        s_bb[tid] = bB1[gr] + bB2[gr];
    }
    if (tid < HN) {
        const float neg1 = __uint_as_float(0xFFFFFFFFu);
        s_msgA[0][tid] = make_float2(hA0[tid], neg1);  // tag -1, read at tick 0
        s_msgB[0][tid] = make_float2(0.f,      neg1);  // discarded read at tick 0
        s_msgA[1][tid] = make_float2(0.f, __uint_as_float(0x80000000u)); // poison tag
        s_msgB[1][tid] = make_float2(0.f, __uint_as_float(0x80000000u));
    }
    const bool isA = (tid < 16);
    const bool isB = (tid >= 32 && tid < 48);
    float cAr = 0.f, cBr = 0.f, hB_init = 0.f;
    if (isA) cAr = cA0[(c << 4) + tid];
    if (isB) { cBr = cB0[(c << 4) + tid - 32]; hB_init = hB0[(c << 4) + tid - 32]; }
    __syncthreads();
    CLUSTER_SYNC_();   // all CTAs initialized before any remote store

    // ---- producer remote addresses: msgX[buf][j] on each rank ----
    uint32_t pdst[2][8];
    if (isA || isB) {
        const int jj = isA ? tid : (tid - 32);
        const int j  = (c << 4) + jj;
#pragma unroll
        for (int buf = 0; buf < 2; buf++) {
            const float2* base = isA ? &s_msgA[buf][j] : &s_msgB[buf][j];
#pragma unroll
            for (int rk = 0; rk < 8; rk++) pdst[buf][rk] = mapa_u32(base, rk);
        }
    }

    // ---- spinner local addresses: tid<128 -> A slot tid; 128..255 -> B ----
    uint32_t spin_addr[2];
    const bool is_spin = (tid < 256);
    if (is_spin) {
        const int slot = tid & 127;
        const float2* b0 = (tid < 128) ? &s_msgA[0][slot] : &s_msgB[0][slot];
        const float2* b1 = (tid < 128) ? &s_msgA[1][slot] : &s_msgB[1][slot];
        spin_addr[0] = (uint32_t)__cvta_generic_to_shared(b0);
        spin_addr[1] = (uint32_t)__cvta_generic_to_shared(b1);
    }
    float* lin_dst = (tid < 128) ? &s_hA[tid & 127] : &s_hB[tid & 127];

    // ---- GA prefetch (mat==0 half==0 lanes) ----
    const bool is_ga = (mat == 0) && (half == 0);
    float ga_cur = 0.f, ga_next = 0.f;
    if (is_ga) ga_cur = g_GA[grow];

    const size_t OH = (size_t)SEQN * HN;

    for (int t = 0; t <= SEQN; t++) {
        const int pb = t & 1;

        // issue next GA load early (overlaps spin + matvec)
        if (is_ga)
            ga_next = (t + 1 < SEQN) ? __ldg(&g_GA[(size_t)(t + 1) * G4 + grow]) : 0.f;

        // ===== spin until this tick's h has landed, copy to lin =====
        if (is_spin) {
            const uint32_t want = (uint32_t)(t - 1);
            const uint32_t ad = spin_addr[pb];
            u64 v;
            do { v = ld_msg(ad); } while ((uint32_t)(v >> 32) != want);
            *lin_dst = __uint_as_float((uint32_t)v);
        }
        __syncthreads();

        // ===== merged matvec (FFMA2): u=WA2*hA(t-1), w=WB1*hA(t-1), v=WB2*hB(t-2)
        {
            const float* hsrc = (mat == 2) ? s_hB : s_hA;
            const ulonglong2* hv = (const ulonglong2*)(hsrc + half * 64);
            u64 a0 = 0ULL, a1 = 0ULL;
#pragma unroll
            for (int k = 0; k < 16; k++) {
                ulonglong2 h2 = hv[k];
                FMA2(a0, wv[2*k],     h2.x);
                FMA2(a1, wv[2*k + 1], h2.y);
            }
            float2 f0 = *(float2*)&a0, f1 = *(float2*)&a1;
            float s = (f0.x + f0.y) + (f1.x + f1.y);
            s += __shfl_down_sync(0xffffffffu, s, 1);
            if (half == 0) {
                if (mat == 0)      s_uA[r] = s + ga_cur;
                else if (mat == 1) s_wB[r] = s;
                else               s_vB[r] = s;
            }
        }
        __syncthreads();

        // ===== cell A (step t) =====
        if (isA && t < SEQN) {
            const float gi = s_uA[tid];
            const float gf = s_uA[16 + tid];
            const float gg = s_uA[32 + tid];
            const float go = s_uA[48 + tid];
            const float cn = sigm(gf) * cAr + sigm(gi) * tanh_(gg);
            cAr = cn;
            const float h = sigm(go) * tanh_(cn);
#pragma unroll
            for (int rk = 0; rk < 8; rk++) st_msg(pdst[pb ^ 1][rk], h, (uint32_t)t);
            if (write_states && t == SEQN - 1) {
                const int j = (c << 4) + tid;
                out[OH + j]      = h;
                out[OH + HN + j] = cn;
            }
        }

        // ===== cell B (step t-1) =====
        if (isB) {
            const int ln = tid - 32;
            float h, cn = cBr;
            if (t == 0) {
                h = hB_init;
            } else {
                const float gi = s_wB[ln]      + s_vB[ln]      + s_bb[ln];
                const float gf = s_wB[16 + ln] + s_vB[16 + ln] + s_bb[16 + ln];
                const float gg = s_wB[32 + ln] + s_vB[32 + ln] + s_bb[32 + ln];
                const float go = s_wB[48 + ln] + s_vB[48 + ln] + s_bb[48 + ln];
                cn = sigm(gf) * cBr + sigm(gi) * tanh_(gg);
                cBr = cn;
                h = sigm(go) * tanh_(cn);
            }
            if (t < SEQN) {
#pragma unroll
                for (int rk = 0; rk < 8; rk++) st_msg(pdst[pb ^ 1][rk], h, (uint32_t)t);
            }
            if (t >= 1) {
                const int j = (c << 4) + ln;
                g_HB[(size_t)(t - 1) * HN + j] = h;
                if (write_states && t == SEQN) {
                    out[OH + 2 * HN + j] = h;
                    out[OH + 3 * HN + j] = cn;
                }
            }
        }

        if (is_ga) ga_cur = ga_next;
    }

    CLUSTER_SYNC_();   // keep peers' SMEM alive until all remote traffic done
}

// ---------------------------------------------------------------------------
// Kernel 3: logits[t] = hB[t] @ Wfc^T + bfc
// ---------------------------------------------------------------------------
__global__ void __launch_bounds__(128) fc_kernel(const float* __restrict__ W,
                                                 const float* __restrict__ b,
                                                 float* __restrict__ out) {
    __shared__ float hs[64 * 128];
    const int tid = threadIdx.x;

    float4 w[32];
    const float4* wg = (const float4*)(W + (size_t)tid * 128);
#pragma unroll
    for (int k = 0; k < 32; k++) w[k] = wg[k];
    const float bias = b[tid];

    const int t0 = blockIdx.x * 64;
    const float4* hg = (const float4*)(g_HB + (size_t)t0 * 128);
    float4* hs4 = (float4*)hs;
#pragma unroll
    for (int i = 0; i < 16; i++) hs4[tid + (i << 7)] = hg[tid + (i << 7)];
    __syncthreads();

    for (int tt = 0; tt < 64; tt++) {
        const float4* hx = (const float4*)(hs + tt * 128);
        float a0 = 0.f, a1 = 0.f, a2 = 0.f, a3 = 0.f;
#pragma unroll
        for (int k = 0; k < 32; k++) {
            float4 h = hx[k];
            a0 = fmaf(w[k].x, h.x, a0);
            a1 = fmaf(w[k].y, h.y, a1);
            a2 = fmaf(w[k].z, h.z, a2);
            a3 = fmaf(w[k].w, h.w, a3);
        }
        out[(size_t)(t0 + tt) * 128 + tid] = (a0 + a1) + (a2 + a3) + bias;
    }
}

// ---------------------------------------------------------------------------
// launch
// ---------------------------------------------------------------------------
extern "C" void kernel_launch(void* const* d_in, const int* in_sizes, int n_in,
                              void* d_out, int out_size) {
    const float* x   = (const float*)d_in[0];
    const float* hA0 = (const float*)d_in[1];
    const float* cA0 = (const float*)d_in[2];
    const float* hB0 = (const float*)d_in[3];
    const float* cB0 = (const float*)d_in[4];
    const float* WA1 = (const float*)d_in[5];
    const float* bA1 = (const float*)d_in[6];
    const float* WA2 = (const float*)d_in[7];
    const float* bA2 = (const float*)d_in[8];
    const float* WB1 = (const float*)d_in[9];
    const float* bB1 = (const float*)d_in[10];
    const float* WB2 = (const float*)d_in[11];
    const float* bB2 = (const float*)d_in[12];
    const float* Wfc = (const float*)d_in[13];
    const float* bfc = (const float*)d_in[14];
    float* out = (float*)d_out;

    const int write_states = (out_size >= SEQN * HN + 4 * HN) ? 1 : 0;

    ga_kernel<<<dim3(SEQN / 64, 4), 128>>>(x, WA1, bA1, bA2);
    recur_kernel<<<8, 384>>>(WA2, WB1, WB2, bB1, bB2, hA0, cA0, hB0, cB0, out,
                             write_states);
    fc_kernel<<<SEQN / 64, 128>>>(Wfc, bfc, out);
}

// round 5
// speedup vs baseline: 1.8756x; 1.4381x over previous
#include <cuda_runtime.h>
#include <cstdint>

#define SEQN 65536
#define HN   128
#define G4   512   // 4*H

typedef unsigned long long u64;

// Scratch (device globals: allocation-free per harness rules)
__device__ float g_GA[(size_t)SEQN * G4];   // precomputed x@WA1^T + bA1 + bA2
__device__ float g_HB[(size_t)SEQN * HN];   // hB per step, consumed by fc GEMM

// ---------------------------------------------------------------------------
// helpers
// ---------------------------------------------------------------------------
__device__ __forceinline__ float sigm(float x) {
    return __fdividef(1.f, 1.f + __expf(-x));
}
__device__ __forceinline__ float tanhfast(float x) {
    float y;
    asm("tanh.approx.f32 %0, %1;" : "=f"(y) : "f"(x));
    return y;
}
__device__ __forceinline__ float sigmfast(float x) {
    return fmaf(tanhfast(0.5f * x), 0.5f, 0.5f);
}

__device__ __forceinline__ uint32_t mapa_u32(const void* p, int rank) {
    uint32_t a = (uint32_t)__cvta_generic_to_shared(p), r;
    asm("mapa.shared::cluster.u32 %0, %1, %2;" : "=r"(r) : "r"(a), "r"(rank));
    return r;
}

#define ST_CLUSTER_F32(addr, v) \
    asm volatile("st.shared::cluster.f32 [%0], %1;" :: "r"(addr), "f"(v) : "memory")

#define ARRIVE_REL_CLUSTER(addr) \
    asm volatile("mbarrier.arrive.release.cluster.shared::cluster.b64 _, [%0];" \
                 :: "r"(addr) : "memory")

#define MBAR_INIT(addr, cnt) \
    asm volatile("mbarrier.init.shared.b64 [%0], %1;" :: "r"(addr), "r"(cnt) : "memory")

__device__ __forceinline__ void wait_parity(uint32_t mbar, uint32_t par) {
    uint32_t done;
    do {
        asm volatile(
            "{\n\t.reg .pred p;\n\t"
            "mbarrier.try_wait.parity.acquire.cluster.shared::cta.b64 p, [%1], %2, 0x989680;\n\t"
            "selp.b32 %0, 1, 0, p;\n\t}"
            : "=r"(done) : "r"(mbar), "r"(par) : "memory");
    } while (!done);
}

#define FMA2(acc, w, h) \
    asm("fma.rn.f32x2 %0, %1, %2, %0;" : "+l"(acc) : "l"(w), "l"(h))

#define CLUSTER_SYNC_()                                                        \
    do {                                                                       \
        asm volatile("barrier.cluster.arrive.aligned;" ::: "memory");          \
        asm volatile("barrier.cluster.wait.aligned;"   ::: "memory");          \
    } while (0)

// ---------------------------------------------------------------------------
// Kernel 1: GA[t, 512] = x[t] @ WA1^T + bA1 + bA2
// ---------------------------------------------------------------------------
__global__ void __launch_bounds__(128) ga_kernel(const float* __restrict__ x,
                                                 const float* __restrict__ W,
                                                 const float* __restrict__ b1,
                                                 const float* __restrict__ b2) {
    __shared__ float xs[64 * 128];
    const int tid = threadIdx.x;
    const int row = (blockIdx.y << 7) + tid;

    float4 w[32];
    const float4* wg = (const float4*)(W + (size_t)row * 128);
#pragma unroll
    for (int k = 0; k < 32; k++) w[k] = wg[k];
    const float bias = b1[row] + b2[row];

    const int t0 = blockIdx.x * 64;
    const float4* xg = (const float4*)(x + (size_t)t0 * 128);
    float4* xs4 = (float4*)xs;
#pragma unroll
    for (int i = 0; i < 16; i++) xs4[tid + (i << 7)] = xg[tid + (i << 7)];
    __syncthreads();

    for (int tt = 0; tt < 64; tt++) {
        const float4* hx = (const float4*)(xs + tt * 128);
        float a0 = 0.f, a1 = 0.f, a2 = 0.f, a3 = 0.f;
#pragma unroll
        for (int k = 0; k < 32; k++) {
            float4 h = hx[k];
            a0 = fmaf(w[k].x, h.x, a0);
            a1 = fmaf(w[k].y, h.y, a1);
            a2 = fmaf(w[k].z, h.z, a2);
            a3 = fmaf(w[k].w, h.w, a3);
        }
        g_GA[(size_t)(t0 + tt) * G4 + row] = (a0 + a1) + (a2 + a3) + bias;
    }
}

// ---------------------------------------------------------------------------
// Kernel 2: pipelined recurrence (B one tick behind A). 8-CTA cluster, 384 thr.
// Tick: wait(bar[pb]) done last iter -> matvec (FFMA2) -> __syncthreads ->
// activations (A warp0 / B warp1 in parallel) -> remote h stores ->
// __syncwarp -> lanes 0-7 remote arrive.release (1 per rank) -> all threads
// try_wait (HW sleep). Barrier count = 16 (2 warps x 8 CTAs), two barriers
// alternating, parity (t>>1)&1.
// ---------------------------------------------------------------------------
__global__ void __cluster_dims__(8, 1, 1) __launch_bounds__(384, 1)
recur_kernel(const float* __restrict__ WA2, const float* __restrict__ WB1,
             const float* __restrict__ WB2, const float* __restrict__ bB1,
             const float* __restrict__ bB2, const float* __restrict__ hA0,
             const float* __restrict__ cA0, const float* __restrict__ hB0,
             const float* __restrict__ cB0, float* __restrict__ out,
             int write_states) {
    __shared__ alignas(16) float s_hA[2][HN];
    __shared__ alignas(16) float s_hB[2][HN];
    __shared__ float s_uA[64];   // WA2 dots (+GA)
    __shared__ float s_wB[64];   // WB1 dots
    __shared__ float s_vB[64];   // WB2 dots
    __shared__ float s_bb[64];   // bB1+bB2
    __shared__ alignas(8) u64 s_bar[2];

    const int c    = blockIdx.x;
    const int tid  = threadIdx.x;
    const int rs   = tid >> 1;      // 0..191
    const int half = tid & 1;
    const int mat  = rs >> 6;       // 0:WA2 1:WB1 2:WB2
    const int r    = rs & 63;
    const int grow = ((r >> 4) << 7) + (c << 4) + (r & 15);

    // ---- weights as packed f32x2 ----
    const float* Wp = (mat == 0) ? WA2 : (mat == 1) ? WB1 : WB2;
    u64 wv[32];
    {
        const ulonglong2* wg = (const ulonglong2*)(Wp + (size_t)grow * 128 + half * 64);
#pragma unroll
        for (int k = 0; k < 16; k++) { ulonglong2 q = wg[k]; wv[2*k] = q.x; wv[2*k+1] = q.y; }
    }

    // ---- init SMEM ----
    if (tid < 64) {
        const int gr = ((tid >> 4) << 7) + (c << 4) + (tid & 15);
        s_bb[tid] = bB1[gr] + bB2[gr];
    }
    if (tid < HN) {
        s_hA[0][tid] = hA0[tid];   // read at tick 0
        s_hB[0][tid] = 0.f;        // discarded read at tick 0
        s_hB[1][tid] = hB0[tid];   // read at tick 1
    }
    if (tid == 0) {
        MBAR_INIT((uint32_t)__cvta_generic_to_shared(&s_bar[0]), 16);
        MBAR_INIT((uint32_t)__cvta_generic_to_shared(&s_bar[1]), 16);
    }
    const bool isA = (tid < 16);
    const bool isB = (tid >= 32 && tid < 48);
    float cAr = 0.f, cBr = 0.f, hB_init = 0.f;
    if (isA) cAr = cA0[(c << 4) + tid];
    if (isB) { cBr = cB0[(c << 4) + tid - 32]; hB_init = hB0[(c << 4) + tid - 32]; }
    __syncthreads();
    CLUSTER_SYNC_();   // all CTAs' SMEM + barriers initialized

    // ---- producer remote h addresses ----
    uint32_t pdst[2][8];   // [buffer][rank]
    if (isA || isB) {
        const int jj = isA ? tid : (tid - 32);
        const int j  = (c << 4) + jj;
#pragma unroll
        for (int buf = 0; buf < 2; buf++) {
            const float* base = isA ? &s_hA[buf][j] : &s_hB[buf][j];
#pragma unroll
            for (int rk = 0; rk < 8; rk++) pdst[buf][rk] = mapa_u32(base, rk);
        }
    }
    // ---- arrive addresses: producer lanes 0-7 of warps 0 and 1 ----
    const int  lane     = tid & 31;
    const bool is_arr   = (tid < 8) || (tid >= 32 && tid < 40);
    uint32_t adst[2];
    if (is_arr) {
        adst[0] = mapa_u32(&s_bar[0], lane);
        adst[1] = mapa_u32(&s_bar[1], lane);
    }
    uint32_t bloc[2];
    bloc[0] = (uint32_t)__cvta_generic_to_shared(&s_bar[0]);
    bloc[1] = (uint32_t)__cvta_generic_to_shared(&s_bar[1]);

    // ---- GA prefetch, distance 2 (mat==0 half==0 lanes) ----
    const bool is_ga = (mat == 0) && (half == 0);
    float ga0 = 0.f, ga1 = 0.f;
    if (is_ga) {
        ga0 = g_GA[grow];
        ga1 = __ldg(&g_GA[(size_t)G4 + grow]);
    }

    const size_t OH = (size_t)SEQN * HN;

    for (int t = 0; t <= SEQN; t++) {
        const int pb = t & 1;

        float ga2 = 0.f;
        if (is_ga && t + 2 < SEQN)
            ga2 = __ldg(&g_GA[(size_t)(t + 2) * G4 + grow]);

        // ===== merged matvec (FFMA2): u=WA2*hA(t-1), w=WB1*hA(t-1), v=WB2*hB(t-2)
        {
            const float* hsrc = (mat == 2) ? s_hB[pb] : s_hA[pb];
            const ulonglong2* hv = (const ulonglong2*)(hsrc + half * 64);
            u64 a0 = 0ULL, a1 = 0ULL;
#pragma unroll
            for (int k = 0; k < 16; k++) {
                ulonglong2 h2 = hv[k];
                FMA2(a0, wv[2*k],     h2.x);
                FMA2(a1, wv[2*k + 1], h2.y);
            }
            float2 f0 = *(float2*)&a0, f1 = *(float2*)&a1;
            float s = (f0.x + f0.y) + (f1.x + f1.y);
            s += __shfl_down_sync(0xffffffffu, s, 1);
            if (half == 0) {
                if (mat == 0)      s_uA[r] = s + ga0;
                else if (mat == 1) s_wB[r] = s;
                else               s_vB[r] = s;
            }
        }
        __syncthreads();

        // ===== cell A (step t), warp 0 =====
        if (tid < 32) {
            float h = 0.f;
            if (isA) {
                const float gi = s_uA[tid];
                const float gf = s_uA[16 + tid];
                const float gg = s_uA[32 + tid];
                const float go = s_uA[48 + tid];
                const float cn = sigmfast(gf) * cAr + sigmfast(gi) * tanhfast(gg);
                cAr = cn;
                h = sigmfast(go) * tanhfast(cn);
#pragma unroll
                for (int rk = 0; rk < 8; rk++) ST_CLUSTER_F32(pdst[pb ^ 1][rk], h);
            }
            __syncwarp();
            if (tid < 8) ARRIVE_REL_CLUSTER(adst[pb]);
            if (isA && write_states && t == SEQN - 1) {
                const int j = (c << 4) + tid;
                out[OH + j]      = h;
                out[OH + HN + j] = cAr;
            }
        }

        // ===== cell B (step t-1), warp 1 =====
        if (tid >= 32 && tid < 64) {
            float h = 0.f, cn = cBr;
            if (isB) {
                const int ln = tid - 32;
                if (t == 0) {
                    h = hB_init;
                } else {
                    const float gi = s_wB[ln]      + s_vB[ln]      + s_bb[ln];
                    const float gf = s_wB[16 + ln] + s_vB[16 + ln] + s_bb[16 + ln];
                    const float gg = s_wB[32 + ln] + s_vB[32 + ln] + s_bb[32 + ln];
                    const float go = s_wB[48 + ln] + s_vB[48 + ln] + s_bb[48 + ln];
                    cn = sigmfast(gf) * cBr + sigmfast(gi) * tanhfast(gg);
                    cBr = cn;
                    h = sigmfast(go) * tanhfast(cn);
                }
#pragma unroll
                for (int rk = 0; rk < 8; rk++) ST_CLUSTER_F32(pdst[pb ^ 1][rk], h);
            }
            __syncwarp();
            if (tid < 40) ARRIVE_REL_CLUSTER(adst[pb]);
            if (isB && t >= 1) {
                const int j = (c << 4) + (tid - 32);
                g_HB[(size_t)(t - 1) * HN + j] = h;
                if (write_states && t == SEQN) {
                    out[OH + 2 * HN + j] = h;
                    out[OH + 3 * HN + j] = cn;
                }
            }
        }

        // ===== tick barrier (HW-sleep wait) =====
        wait_parity(bloc[pb], (uint32_t)((t >> 1) & 1));

        if (is_ga) { ga0 = ga1; ga1 = ga2; }
    }

    CLUSTER_SYNC_();   // keep peers' SMEM alive until all remote traffic done
}

// ---------------------------------------------------------------------------
// Kernel 3: logits[t] = hB[t] @ Wfc^T + bfc
// ---------------------------------------------------------------------------
__global__ void __launch_bounds__(128) fc_kernel(const float* __restrict__ W,
                                                 const float* __restrict__ b,
                                                 float* __restrict__ out) {
    __shared__ float hs[64 * 128];
    const int tid = threadIdx.x;

    float4 w[32];
    const float4* wg = (const float4*)(W + (size_t)tid * 128);
#pragma unroll
    for (int k = 0; k < 32; k++) w[k] = wg[k];
    const float bias = b[tid];

    const int t0 = blockIdx.x * 64;
    const float4* hg = (const float4*)(g_HB + (size_t)t0 * 128);
    float4* hs4 = (float4*)hs;
#pragma unroll
    for (int i = 0; i < 16; i++) hs4[tid + (i << 7)] = hg[tid + (i << 7)];
    __syncthreads();

    for (int tt = 0; tt < 64; tt++) {
        const float4* hx = (const float4*)(hs + tt * 128);
        float a0 = 0.f, a1 = 0.f, a2 = 0.f, a3 = 0.f;
#pragma unroll
        for (int k = 0; k < 32; k++) {
            float4 h = hx[k];
            a0 = fmaf(w[k].x, h.x, a0);
            a1 = fmaf(w[k].y, h.y, a1);
            a2 = fmaf(w[k].z, h.z, a2);
            a3 = fmaf(w[k].w, h.w, a3);
        }
        out[(size_t)(t0 + tt) * 128 + tid] = (a0 + a1) + (a2 + a3) + bias;
    }
}

// ---------------------------------------------------------------------------
// launch
// ---------------------------------------------------------------------------
extern "C" void kernel_launch(void* const* d_in, const int* in_sizes, int n_in,
                              void* d_out, int out_size) {
    const float* x   = (const float*)d_in[0];
    const float* hA0 = (const float*)d_in[1];
    const float* cA0 = (const float*)d_in[2];
    const float* hB0 = (const float*)d_in[3];
    const float* cB0 = (const float*)d_in[4];
    const float* WA1 = (const float*)d_in[5];
    const float* bA1 = (const float*)d_in[6];
    const float* WA2 = (const float*)d_in[7];
    const float* bA2 = (const float*)d_in[8];
    const float* WB1 = (const float*)d_in[9];
    const float* bB1 = (const float*)d_in[10];
    const float* WB2 = (const float*)d_in[11];
    const float* bB2 = (const float*)d_in[12];
    const float* Wfc = (const float*)d_in[13];
    const float* bfc = (const float*)d_in[14];
    float* out = (float*)d_out;

    const int write_states = (out_size >= SEQN * HN + 4 * HN) ? 1 : 0;

    ga_kernel<<<dim3(SEQN / 64, 4), 128>>>(x, WA1, bA1, bA2);
    recur_kernel<<<8, 384>>>(WA2, WB1, WB2, bB1, bB2, hA0, cA0, hB0, cB0, out,
                             write_states);
    fc_kernel<<<SEQN / 64, 128>>>(Wfc, bfc, out);
}

// round 6
// speedup vs baseline: 2.1322x; 1.1368x over previous
#include <cuda_runtime.h>
#include <cstdint>

#define SEQN 65536
#define HN   128
#define G4   512   // 4*H

typedef unsigned long long u64;

// Scratch (device globals: allocation-free per harness rules)
__device__ float g_GA[(size_t)SEQN * G4];   // x@WA1^T + bA1 + bA2
__device__ float g_HB[(size_t)SEQN * HN];   // hB per step (fc input)
__device__ u64   g_msg[(size_t)SEQN * HN];  // {hA:f32(lo), tick:u32(hi)} A->B bridge

// ---------------------------------------------------------------------------
// helpers
// ---------------------------------------------------------------------------
__device__ __forceinline__ float tanhfast(float x) {
    float y;
    asm("tanh.approx.f32 %0, %1;" : "=f"(y) : "f"(x));
    return y;
}
__device__ __forceinline__ float sigmfast(float x) {
    return fmaf(tanhfast(0.5f * x), 0.5f, 0.5f);
}

__device__ __forceinline__ uint32_t mapa_u32(const void* p, int rank) {
    uint32_t a = (uint32_t)__cvta_generic_to_shared(p), r;
    asm("mapa.shared::cluster.u32 %0, %1, %2;" : "=r"(r) : "r"(a), "r"(rank));
    return r;
}

#define ST_CLUSTER_F32(addr, v) \
    asm volatile("st.shared::cluster.f32 [%0], %1;" :: "r"(addr), "f"(v) : "memory")

#define FMA2(acc, w, h) \
    asm("fma.rn.f32x2 %0, %1, %2, %0;" : "+l"(acc) : "l"(w), "l"(h))

#define CLUSTER_ARRIVE_() asm volatile("barrier.cluster.arrive.aligned;" ::: "memory")
#define CLUSTER_WAIT_()   asm volatile("barrier.cluster.wait.aligned;"   ::: "memory")
#define CLUSTER_SYNC_()   do { CLUSTER_ARRIVE_(); CLUSTER_WAIT_(); } while (0)

__device__ __forceinline__ uint32_t ctarank() {
    uint32_t r;
    asm("mov.u32 %0, %%cluster_ctarank;" : "=r"(r));
    return r;
}

// ---------------------------------------------------------------------------
// Kernel 0: reset the A->B message tags (race-free across graph replays)
// ---------------------------------------------------------------------------
__global__ void __launch_bounds__(256) reset_kernel() {
    const size_t N = (size_t)SEQN * HN;
    size_t i = (size_t)blockIdx.x * blockDim.x + threadIdx.x;
    const size_t stride = (size_t)gridDim.x * blockDim.x;
    for (; i < N; i += stride) g_msg[i] = 0xFFFFFFFF00000000ULL;  // tag = -1
}

// ---------------------------------------------------------------------------
// Kernel 1: GA[t, 512] = x[t] @ WA1^T + bA1 + bA2
// ---------------------------------------------------------------------------
__global__ void __launch_bounds__(128) ga_kernel(const float* __restrict__ x,
                                                 const float* __restrict__ W,
                                                 const float* __restrict__ b1,
                                                 const float* __restrict__ b2) {
    __shared__ float xs[64 * 128];
    const int tid = threadIdx.x;
    const int row = (blockIdx.y << 7) + tid;

    float4 w[32];
    const float4* wg = (const float4*)(W + (size_t)row * 128);
#pragma unroll
    for (int k = 0; k < 32; k++) w[k] = wg[k];
    const float bias = b1[row] + b2[row];

    const int t0 = blockIdx.x * 64;
    const float4* xg = (const float4*)(x + (size_t)t0 * 128);
    float4* xs4 = (float4*)xs;
#pragma unroll
    for (int i = 0; i < 16; i++) xs4[tid + (i << 7)] = xg[tid + (i << 7)];
    __syncthreads();

    for (int tt = 0; tt < 64; tt++) {
        const float4* hx = (const float4*)(xs + tt * 128);
        float a0 = 0.f, a1 = 0.f, a2 = 0.f, a3 = 0.f;
#pragma unroll
        for (int k = 0; k < 32; k++) {
            float4 h = hx[k];
            a0 = fmaf(w[k].x, h.x, a0);
            a1 = fmaf(w[k].y, h.y, a1);
            a2 = fmaf(w[k].z, h.z, a2);
            a3 = fmaf(w[k].w, h.w, a3);
        }
        g_GA[(size_t)(t0 + tt) * G4 + row] = (a0 + a1) + (a2 + a3) + bias;
    }
}

// ---------------------------------------------------------------------------
// Kernel 2: split-chain recurrence. grid=16, cluster=8 -> TWO clusters.
//   Cluster A (blocks 0-7):  hA chain. 64 WA2 rows/CTA in quarters (256 thr).
//     Publishes {hA, t} as one 8B volatile GMEM store per element.
//   Cluster B (blocks 8-15): hB chain. 128 rows/CTA (WB1|WB2) in halves
//     (256 thr) + 128 spinner threads staging hA(t+1) from L2 during tick t.
// Each cluster syncs ONLY itself with barrier.cluster (R2-proven).
// ---------------------------------------------------------------------------
__global__ void __cluster_dims__(8, 1, 1) __launch_bounds__(384, 1)
recur_kernel(const float* __restrict__ WA2, const float* __restrict__ WB1,
             const float* __restrict__ WB2, const float* __restrict__ bB1,
             const float* __restrict__ bB2, const float* __restrict__ hA0,
             const float* __restrict__ cA0, const float* __restrict__ hB0,
             const float* __restrict__ cB0, float* __restrict__ out,
             int write_states) {
    __shared__ alignas(16) float s_h[2][HN];    // A: hA bufs | B: hB bufs
    __shared__ alignas(16) float s_hX[2][HN];   // B only: staged hA
    __shared__ float s_d0[64];                  // A: u dots | B: WB1 dots
    __shared__ float s_d1[64];                  // B: WB2 dots
    __shared__ float s_bb[64];                  // B: bB1+bB2

    const int c   = (int)ctarank();
    const int tid = threadIdx.x;
    const size_t OH = (size_t)SEQN * HN;

    if (blockIdx.x < 8) {
        // ==================== ROLE A: hA chain ====================
        const int rs = tid >> 2;          // row 0..63
        const int q  = tid & 3;           // quarter (32 cols)
        const int grow = ((rs >> 4) << 7) + (c << 4) + (rs & 15);

        u64 wv[16];
        if (tid < 256) {
            const ulonglong2* wg = (const ulonglong2*)(WA2 + (size_t)grow * 128 + q * 32);
#pragma unroll
            for (int k = 0; k < 8; k++) { ulonglong2 p = wg[k]; wv[2*k] = p.x; wv[2*k+1] = p.y; }
        }
        if (tid < HN) s_h[0][tid] = hA0[tid];
        float cAr = 0.f;
        if (tid < 16) cAr = cA0[(c << 4) + tid];

        uint32_t pdst[2][8];
        if (tid < 16) {
            const int j = (c << 4) + tid;
#pragma unroll
            for (int buf = 0; buf < 2; buf++)
#pragma unroll
                for (int rk = 0; rk < 8; rk++) pdst[buf][rk] = mapa_u32(&s_h[buf][j], rk);
        }
        __syncthreads();
        CLUSTER_SYNC_();

        const bool is_ga = (tid < 256) && (q == 0);
        float ga0 = 0.f, ga1 = 0.f;
        if (is_ga) {
            ga0 = g_GA[grow];
            ga1 = __ldg(&g_GA[(size_t)G4 + grow]);
        }

        for (int t = 0; t < SEQN; t++) {
            const int pb = t & 1;
            float ga2 = 0.f;
            if (is_ga && t + 2 < SEQN)
                ga2 = __ldg(&g_GA[(size_t)(t + 2) * G4 + grow]);

            if (tid < 256) {
                const ulonglong2* hv = (const ulonglong2*)(s_h[pb] + q * 32);
                u64 a0 = 0ULL, a1 = 0ULL;
#pragma unroll
                for (int k = 0; k < 8; k++) {
                    ulonglong2 h2 = hv[k];
                    FMA2(a0, wv[2*k],     h2.x);
                    FMA2(a1, wv[2*k + 1], h2.y);
                }
                float2 f0 = *(float2*)&a0, f1 = *(float2*)&a1;
                float s = (f0.x + f0.y) + (f1.x + f1.y);
                s += __shfl_down_sync(0xffffffffu, s, 1);
                s += __shfl_down_sync(0xffffffffu, s, 2);
                if (q == 0) s_d0[rs] = s + ga0;
            }
            __syncthreads();

            if (tid < 16) {
                const float gi = s_d0[tid];
                const float gf = s_d0[16 + tid];
                const float gg = s_d0[32 + tid];
                const float go = s_d0[48 + tid];
                const float cn = sigmfast(gf) * cAr + sigmfast(gi) * tanhfast(gg);
                cAr = cn;
                const float h = sigmfast(go) * tanhfast(cn);
#pragma unroll
                for (int rk = 0; rk < 8; rk++) ST_CLUSTER_F32(pdst[pb ^ 1][rk], h);
                // publish {h, t} to chain B (single 8B atomic store)
                const int j = (c << 4) + tid;
                const u64 m = (u64)__float_as_uint(h) | ((u64)(uint32_t)t << 32);
                *((volatile u64*)&g_msg[(size_t)t * HN + j]) = m;
                if (write_states && t == SEQN - 1) {
                    out[OH + j]      = h;
                    out[OH + HN + j] = cn;
                }
            }
            CLUSTER_ARRIVE_();
            if (is_ga) { ga0 = ga1; ga1 = ga2; }
            CLUSTER_WAIT_();
        }
        CLUSTER_SYNC_();
    } else {
        // ==================== ROLE B: hB chain ====================
        const int rs   = tid >> 1;        // 0..127
        const int half = tid & 1;
        const int mat  = rs >> 6;         // 0: WB1 (reads hA), 1: WB2 (reads hB)
        const int r    = rs & 63;
        const int grow = ((r >> 4) << 7) + (c << 4) + (r & 15);

        u64 wv[32];
        if (tid < 256) {
            const float* Wp = mat ? WB2 : WB1;
            const ulonglong2* wg = (const ulonglong2*)(Wp + (size_t)grow * 128 + half * 64);
#pragma unroll
            for (int k = 0; k < 16; k++) { ulonglong2 p = wg[k]; wv[2*k] = p.x; wv[2*k+1] = p.y; }
        }
        if (tid < 64) {
            const int gr = ((tid >> 4) << 7) + (c << 4) + (tid & 15);
            s_bb[tid] = bB1[gr] + bB2[gr];
        }
        if (tid < HN) s_h[0][tid] = hB0[tid];
        float cBr = 0.f;
        if (tid < 16) cBr = cB0[(c << 4) + tid];

        uint32_t pdst[2][8];
        if (tid < 16) {
            const int j = (c << 4) + tid;
#pragma unroll
            for (int buf = 0; buf < 2; buf++)
#pragma unroll
                for (int rk = 0; rk < 8; rk++) pdst[buf][rk] = mapa_u32(&s_h[buf][j], rk);
        }
        __syncthreads();
        CLUSTER_SYNC_();

        // pre-stage hA(0)
        if (tid >= 256) {
            const int slot = tid - 256;
            u64 v;
            do { v = *((volatile u64*)&g_msg[slot]); } while ((uint32_t)(v >> 32) != 0u);
            s_hX[0][slot] = __uint_as_float((uint32_t)v);
        }
        __syncthreads();

        for (int t = 0; t < SEQN; t++) {
            const int pb = t & 1;

            if (tid < 256) {
                const float* hsrc = mat ? s_h[pb] : s_hX[pb];
                const ulonglong2* hv = (const ulonglong2*)(hsrc + half * 64);
                u64 a0 = 0ULL, a1 = 0ULL;
#pragma unroll
                for (int k = 0; k < 16; k++) {
                    ulonglong2 h2 = hv[k];
                    FMA2(a0, wv[2*k],     h2.x);
                    FMA2(a1, wv[2*k + 1], h2.y);
                }
                float2 f0 = *(float2*)&a0, f1 = *(float2*)&a1;
                float s = (f0.x + f0.y) + (f1.x + f1.y);
                s += __shfl_down_sync(0xffffffffu, s, 1);
                if (half == 0) {
                    if (mat == 0) s_d0[r] = s;
                    else          s_d1[r] = s;
                }
            } else if (t + 1 < SEQN) {
                // stage hA(t+1) concurrently with this tick's matvec
                const int slot = tid - 256;
                const uint32_t want = (uint32_t)(t + 1);
                u64 v;
                do { v = *((volatile u64*)&g_msg[(size_t)(t + 1) * HN + slot]); }
                while ((uint32_t)(v >> 32) != want);
                s_hX[(t + 1) & 1][slot] = __uint_as_float((uint32_t)v);
            }
            __syncthreads();

            if (tid < 16) {
                const float gi = s_d0[tid]      + s_d1[tid]      + s_bb[tid];
                const float gf = s_d0[16 + tid] + s_d1[16 + tid] + s_bb[16 + tid];
                const float gg = s_d0[32 + tid] + s_d1[32 + tid] + s_bb[32 + tid];
                const float go = s_d0[48 + tid] + s_d1[48 + tid] + s_bb[48 + tid];
                const float cn = sigmfast(gf) * cBr + sigmfast(gi) * tanhfast(gg);
                cBr = cn;
                const float h = sigmfast(go) * tanhfast(cn);
#pragma unroll
                for (int rk = 0; rk < 8; rk++) ST_CLUSTER_F32(pdst[pb ^ 1][rk], h);
                const int j = (c << 4) + tid;
                g_HB[(size_t)t * HN + j] = h;
                if (write_states && t == SEQN - 1) {
                    out[OH + 2 * HN + j] = h;
                    out[OH + 3 * HN + j] = cn;
                }
            }
            CLUSTER_ARRIVE_();
            CLUSTER_WAIT_();
        }
        CLUSTER_SYNC_();
    }
}

// ---------------------------------------------------------------------------
// Kernel 3: logits[t] = hB[t] @ Wfc^T + bfc
// ---------------------------------------------------------------------------
__global__ void __launch_bounds__(128) fc_kernel(const float* __restrict__ W,
                                                 const float* __restrict__ b,
                                                 float* __restrict__ out) {
    __shared__ float hs[64 * 128];
    const int tid = threadIdx.x;

    float4 w[32];
    const float4* wg = (const float4*)(W + (size_t)tid * 128);
#pragma unroll
    for (int k = 0; k < 32; k++) w[k] = wg[k];
    const float bias = b[tid];

    const int t0 = blockIdx.x * 64;
    const float4* hg = (const float4*)(g_HB + (size_t)t0 * 128);
    float4* hs4 = (float4*)hs;
#pragma unroll
    for (int i = 0; i < 16; i++) hs4[tid + (i << 7)] = hg[tid + (i << 7)];
    __syncthreads();

    for (int tt = 0; tt < 64; tt++) {
        const float4* hx = (const float4*)(hs + tt * 128);
        float a0 = 0.f, a1 = 0.f, a2 = 0.f, a3 = 0.f;
#pragma unroll
        for (int k = 0; k < 32; k++) {
            float4 h = hx[k];
            a0 = fmaf(w[k].x, h.x, a0);
            a1 = fmaf(w[k].y, h.y, a1);
            a2 = fmaf(w[k].z, h.z, a2);
            a3 = fmaf(w[k].w, h.w, a3);
        }
        out[(size_t)(t0 + tt) * 128 + tid] = (a0 + a1) + (a2 + a3) + bias;
    }
}

// ---------------------------------------------------------------------------
// launch
// ---------------------------------------------------------------------------
extern "C" void kernel_launch(void* const* d_in, const int* in_sizes, int n_in,
                              void* d_out, int out_size) {
    const float* x   = (const float*)d_in[0];
    const float* hA0 = (const float*)d_in[1];
    const float* cA0 = (const float*)d_in[2];
    const float* hB0 = (const float*)d_in[3];
    const float* cB0 = (const float*)d_in[4];
    const float* WA1 = (const float*)d_in[5];
    const float* bA1 = (const float*)d_in[6];
    const float* WA2 = (const float*)d_in[7];
    const float* bA2 = (const float*)d_in[8];
    const float* WB1 = (const float*)d_in[9];
    const float* bB1 = (const float*)d_in[10];
    const float* WB2 = (const float*)d_in[11];
    const float* bB2 = (const float*)d_in[12];
    const float* Wfc = (const float*)d_in[13];
    const float* bfc = (const float*)d_in[14];
    float* out = (float*)d_out;

    const int write_states = (out_size >= SEQN * HN + 4 * HN) ? 1 : 0;

    ga_kernel<<<dim3(SEQN / 64, 4), 128>>>(x, WA1, bA1, bA2);
    reset_kernel<<<2048, 256>>>();
    recur_kernel<<<16, 384>>>(WA2, WB1, WB2, bB1, bB2, hA0, cA0, hB0, cB0, out,
                              write_states);
    fc_kernel<<<SEQN / 64, 128>>>(Wfc, bfc, out);
}